// round 3
// baseline (speedup 1.0000x reference)
#include <cuda_runtime.h>

// Problem constants
#define NN 50000   // nodes
#define KK 10      // sampled neighbors per node
#define FF 128     // embedding dim
#define HH 64      // hidden per direction
#define GG 256     // 4*H gate width

#define BF 8       // nodes per CTA (forward)
#define BB 16      // nodes per CTA (backward)

// ---------------- math helpers (fast, ~1e-6 rel err; tolerance is 1e-3) ----
__device__ __forceinline__ float sigf(float x) {
    return __fdividef(1.0f, 1.0f + __expf(-x));
}
__device__ __forceinline__ float tanh_fast(float x) {
    x = fminf(fmaxf(x, -9.0f), 9.0f);           // tanh(9) == 1 at fp32 res
    float e = __expf(-2.0f * x);
    return __fdividef(1.0f - e, 1.0f + e);
}

// ============================================================================
// Forward kernel: full 10-step LSTM, writes out[:, 0:64]
//
// Shared memory (floats):
//   x_s    [8][10][128]        10240   gathered embeddings
//   chunk  [32][257]            8224   WihT chunk (transposed, padded)
//       -- overlay after GEMM:
//       gates [8][256]          2048
//       h_s   [8][64]            512
//   xg     [8][10][256]        20480   precomputed input projections + biases
//   whh_s  [256][65]           16640   Whh padded (conflict-free row reads)
//   total                      55584 floats = 222336 bytes
// ============================================================================
#define FWD_SM_FLOATS 55584

__global__ __launch_bounds__(256, 1)
void lstm_fwd_kernel(const int*   __restrict__ nidx,
                     const float* __restrict__ embed,
                     const float* __restrict__ Wih,
                     const float* __restrict__ Whh,
                     const float* __restrict__ bih,
                     const float* __restrict__ bhh,
                     float*       __restrict__ out)
{
    extern __shared__ float sm[];
    float* x_s   = sm;                    // 10240
    float* chunk = sm + 10240;            // 8224
    float* gates = sm + 10240;            // overlay, 2048
    float* h_s   = sm + 10240 + 2048;     // overlay, 512 (16B aligned)
    float* xg    = sm + 18464;            // 20480
    float* whh_s = sm + 38944;            // 16640

    const int tid  = threadIdx.x;
    const int lane = tid & 31;
    const int wid  = tid >> 5;            // warp id == node within CTA
    const int n0   = blockIdx.x * BF;

    // ---- gather embeddings: warp b loads its node's 10 rows (float4) ----
    {
        int idxv = 0;
        if (lane < KK) idxv = nidx[(n0 + wid) * KK + lane];
        #pragma unroll
        for (int k = 0; k < KK; ++k) {
            int row = __shfl_sync(0xffffffffu, idxv, k);
            float4 v = reinterpret_cast<const float4*>(embed)[row * (FF / 4) + lane];
            reinterpret_cast<float4*>(x_s + (wid * KK + k) * FF)[lane] = v;
        }
    }
    // ---- load Whh into padded smem [256][65] ----
    #pragma unroll 8
    for (int i = 0; i < 64; ++i) {
        int e = tid + i * 256;            // e < 16384
        int r = e >> 6, f = e & 63;
        whh_s[r * 65 + f] = Whh[e];
    }
    __syncthreads();

    // ---- input-projection GEMM: acc[k][j] for node=wid, col = lane+32j ----
    float acc[KK][8];
    #pragma unroll
    for (int k = 0; k < KK; ++k)
        #pragma unroll
        for (int j = 0; j < 8; ++j) acc[k][j] = 0.0f;

    for (int cc = 0; cc < 4; ++cc) {
        const int f0 = cc * 32;
        // stage WihT chunk: chunk[ff][c] = Wih[c][f0+ff]  (coalesced LDG, CF STS)
        #pragma unroll 8
        for (int r = 0; r < 32; ++r) {
            int c = wid * 32 + r;
            chunk[lane * 257 + c] = Wih[c * FF + f0 + lane];
        }
        __syncthreads();

        #pragma unroll
        for (int ff4 = 0; ff4 < 8; ++ff4) {          // 4 f's at a time
            float a[KK][4];
            #pragma unroll
            for (int k = 0; k < KK; ++k) {
                float4 t = *reinterpret_cast<const float4*>(
                    x_s + (wid * KK + k) * FF + f0 + ff4 * 4);
                a[k][0] = t.x; a[k][1] = t.y; a[k][2] = t.z; a[k][3] = t.w;
            }
            #pragma unroll
            for (int u = 0; u < 4; ++u) {
                float w[8];
                #pragma unroll
                for (int j = 0; j < 8; ++j)
                    w[j] = chunk[(ff4 * 4 + u) * 257 + lane + 32 * j];
                #pragma unroll
                for (int k = 0; k < KK; ++k) {
                    float av = a[k][u];
                    #pragma unroll
                    for (int j = 0; j < 8; ++j)
                        acc[k][j] = fmaf(av, w[j], acc[k][j]);
                }
            }
        }
        __syncthreads();
    }

    // ---- epilogue: add biases, store xg ----
    {
        float bsum[8];
        #pragma unroll
        for (int j = 0; j < 8; ++j) {
            int c = lane + 32 * j;
            bsum[j] = bih[c] + bhh[c];
        }
        #pragma unroll
        for (int k = 0; k < KK; ++k)
            #pragma unroll
            for (int j = 0; j < 8; ++j)
                xg[(wid * KK + k) * GG + lane + 32 * j] = acc[k][j] + bsum[j];
    }

    // ---- register-cache this thread's Whh row (col c = tid) ----
    float wreg[64];
    #pragma unroll
    for (int f = 0; f < 64; ++f) wreg[f] = whh_s[tid * 65 + f];

    __syncthreads();   // xg visible everywhere; chunk reads done -> overlay safe

    // ---- recurrence: 10 steps ----
    float cst0 = 0.0f, cst1 = 0.0f, hout0 = 0.0f, hout1 = 0.0f;

    for (int k = 0; k < KK; ++k) {
        // col phase: thread owns gate column c = tid, all 8 nodes
        float g8[8];
        #pragma unroll
        for (int b = 0; b < 8; ++b) g8[b] = xg[(b * KK + k) * GG + tid];
        if (k > 0) {
            #pragma unroll
            for (int b = 0; b < 8; ++b) {
                const float4* h4 = reinterpret_cast<const float4*>(h_s + b * HH);
                float s = g8[b];
                #pragma unroll
                for (int q = 0; q < 16; ++q) {
                    float4 hv = h4[q];
                    s = fmaf(wreg[4 * q + 0], hv.x, s);
                    s = fmaf(wreg[4 * q + 1], hv.y, s);
                    s = fmaf(wreg[4 * q + 2], hv.z, s);
                    s = fmaf(wreg[4 * q + 3], hv.w, s);
                }
                g8[b] = s;
            }
        }
        #pragma unroll
        for (int b = 0; b < 8; ++b) gates[b * GG + tid] = g8[b];
        __syncthreads();

        // cell phase: warp wid owns node wid; lane handles cells lane, lane+32
        {
            float gi0 = gates[wid * GG +   0 + lane];
            float gf0 = gates[wid * GG +  64 + lane];
            float gg0 = gates[wid * GG + 128 + lane];
            float go0 = gates[wid * GG + 192 + lane];
            float gi1 = gates[wid * GG +  32 + lane];
            float gf1 = gates[wid * GG +  96 + lane];
            float gg1 = gates[wid * GG + 160 + lane];
            float go1 = gates[wid * GG + 224 + lane];

            float iv0 = sigf(gi0), fv0 = sigf(gf0), gv0 = tanh_fast(gg0), ov0 = sigf(go0);
            float iv1 = sigf(gi1), fv1 = sigf(gf1), gv1 = tanh_fast(gg1), ov1 = sigf(go1);

            cst0 = (k == 0) ? iv0 * gv0 : fmaf(fv0, cst0, iv0 * gv0);
            cst1 = (k == 0) ? iv1 * gv1 : fmaf(fv1, cst1, iv1 * gv1);
            hout0 = ov0 * tanh_fast(cst0);
            hout1 = ov1 * tanh_fast(cst1);
            h_s[wid * HH +      lane] = hout0;
            h_s[wid * HH + 32 + lane] = hout1;
        }
        __syncthreads();
    }

    // ---- write h_f into out[:, 0:64] ----
    out[(n0 + wid) * (2 * HH) +      lane] = hout0;
    out[(n0 + wid) * (2 * HH) + 32 + lane] = hout1;
}

// ============================================================================
// Backward kernel: single step from h0=c0=0 on x[:, K-1].
// h @ Whh_b == 0 and forget gate multiplies c0=0, so:
//   h_b = sigmoid(o) * tanh( sigmoid(i) * tanh(g) )
// from gates = x_{K-1} @ Wih_b^T + bih_b + bhh_b. Writes out[:, 64:128].
//
// Shared (floats): x2[16][128]=2048, chunk[32][257]=8224, g2[16][256]=4096
//   total 14368 floats = 57472 bytes
// ============================================================================
#define BWD_SM_FLOATS 14368

__global__ __launch_bounds__(256)
void lstm_bwd_kernel(const int*   __restrict__ nidx,
                     const float* __restrict__ embed,
                     const float* __restrict__ Wihb,
                     const float* __restrict__ bihb,
                     const float* __restrict__ bhhb,
                     float*       __restrict__ out)
{
    extern __shared__ float sm[];
    float* x2    = sm;            // 2048
    float* chunk = sm + 2048;     // 8224
    float* g2    = sm + 10272;    // 4096

    const int tid  = threadIdx.x;
    const int lane = tid & 31;
    const int wid  = tid >> 5;
    const int m0   = blockIdx.x * BB;

    // gather x[:, K-1]: warp handles 2 nodes
    #pragma unroll
    for (int r = 0; r < 2; ++r) {
        int node = m0 + wid * 2 + r;
        int idx  = nidx[node * KK + (KK - 1)];
        float4 v = reinterpret_cast<const float4*>(embed)[idx * (FF / 4) + lane];
        reinterpret_cast<float4*>(x2 + (wid * 2 + r) * FF)[lane] = v;
    }
    __syncthreads();

    float acc[2][8];
    #pragma unroll
    for (int r = 0; r < 2; ++r)
        #pragma unroll
        for (int j = 0; j < 8; ++j) acc[r][j] = 0.0f;

    for (int cc = 0; cc < 4; ++cc) {
        const int f0 = cc * 32;
        #pragma unroll 8
        for (int r = 0; r < 32; ++r) {
            int c = wid * 32 + r;
            chunk[lane * 257 + c] = Wihb[c * FF + f0 + lane];
        }
        __syncthreads();
        #pragma unroll 8
        for (int ff = 0; ff < 32; ++ff) {
            float w[8];
            #pragma unroll
            for (int j = 0; j < 8; ++j)
                w[j] = chunk[ff * 257 + lane + 32 * j];
            #pragma unroll
            for (int r = 0; r < 2; ++r) {
                float av = x2[(wid * 2 + r) * FF + f0 + ff];
                #pragma unroll
                for (int j = 0; j < 8; ++j)
                    acc[r][j] = fmaf(av, w[j], acc[r][j]);
            }
        }
        __syncthreads();
    }

    // bias + stage gates
    #pragma unroll
    for (int j = 0; j < 8; ++j) {
        int c = lane + 32 * j;
        float bs = bihb[c] + bhhb[c];
        g2[(wid * 2 + 0) * GG + c] = acc[0][j] + bs;
        g2[(wid * 2 + 1) * GG + c] = acc[1][j] + bs;
    }
    __syncthreads();

    // cell: 16*64 = 1024 cells, 4 per thread (f-gate unused: c0 = 0)
    #pragma unroll
    for (int i = 0; i < 4; ++i) {
        int cell = tid + 256 * i;
        int nb = cell >> 6, j = cell & 63;
        float gi = g2[nb * GG +       j];
        float gg = g2[nb * GG + 128 + j];
        float go = g2[nb * GG + 192 + j];
        float cv = sigf(gi) * tanh_fast(gg);
        out[(m0 + nb) * (2 * HH) + HH + j] = sigf(go) * tanh_fast(cv);
    }
}

// ============================================================================
// Launch
// ============================================================================
extern "C" void kernel_launch(void* const* d_in, const int* in_sizes, int n_in,
                              void* d_out, int out_size)
{
    const int*   nidx  = (const int*)  d_in[0];
    const float* embed = (const float*)d_in[1];
    const float* Wih_f = (const float*)d_in[2];
    const float* Whh_f = (const float*)d_in[3];
    const float* bih_f = (const float*)d_in[4];
    const float* bhh_f = (const float*)d_in[5];
    const float* Wih_b = (const float*)d_in[6];
    // d_in[7] = Whh_b: provably unused (backward stream does exactly one step
    // from h0 = 0, so the recurrent term vanishes)
    const float* bih_b = (const float*)d_in[8];
    const float* bhh_b = (const float*)d_in[9];
    float* out = (float*)d_out;

    const size_t fwd_sm = FWD_SM_FLOATS * sizeof(float);  // 222336 B
    const size_t bwd_sm = BWD_SM_FLOATS * sizeof(float);  //  57472 B

    cudaFuncSetAttribute(lstm_fwd_kernel,
                         cudaFuncAttributeMaxDynamicSharedMemorySize, (int)fwd_sm);
    cudaFuncSetAttribute(lstm_bwd_kernel,
                         cudaFuncAttributeMaxDynamicSharedMemorySize, (int)bwd_sm);

    lstm_fwd_kernel<<<NN / BF, 256, fwd_sm>>>(nidx, embed, Wih_f, Whh_f,
                                              bih_f, bhh_f, out);
    lstm_bwd_kernel<<<NN / BB, 256, bwd_sm>>>(nidx, embed, Wih_b,
                                              bih_b, bhh_b, out);
}